// round 3
// baseline (speedup 1.0000x reference)
#include <cuda_runtime.h>
#include <cuda_bf16.h>
#include <stdint.h>

// Problem constants (fixed by the dataset)
#define N_NODES 50000
#define N_EDGES 800000
#define D_FEAT  128
#define HIDDEN  128

// Scratch (static device globals — no allocation allowed)
__device__ float g_deg [N_NODES];
__device__ float g_dinv[N_NODES];
__device__ float g_h1  [(size_t)N_NODES * HIDDEN];   // x @ W1
__device__ float g_agg [(size_t)N_NODES * HIDDEN];   // scatter-add target, layer 1
__device__ float g_h2  [N_NODES];                    // relu(.) @ W2 per node
__device__ int   g_src32[N_EDGES];                   // int32 edge endpoints
__device__ int   g_dst32[N_EDGES];
__device__ int   g_is64;                             // dtype probe result

// ---------------------------------------------------------------------------
// K_probe: decide whether edge_index is int64 or int32 (JAX x64-disabled
// silently downgrades to int32). Reading int32 data as int64 merges two
// random indices -> value far outside [0, N_NODES).
// ---------------------------------------------------------------------------
__global__ void k_probe(const void* __restrict__ ei) {
    const long long* p = (const long long*)ei;
    int ok64 = 1;
    for (int i = 0; i < 16; i++) {
        long long v = p[i];
        if (v < 0 || v >= N_NODES) { ok64 = 0; break; }
    }
    g_is64 = ok64;
}

// ---------------------------------------------------------------------------
// K0: init — zero agg, deg = 1.0 (self loop); convert edges to int32
// ---------------------------------------------------------------------------
__global__ void k_init(const void* __restrict__ ei) {
    int i = blockIdx.x * blockDim.x + threadIdx.x;
    const int TOT = N_NODES * HIDDEN;
    if (i < TOT) g_agg[i] = 0.0f;
    if (i < N_NODES) g_deg[i] = 1.0f;
    if (i < N_EDGES) {
        int s, d;
        if (g_is64) {
            const long long* p = (const long long*)ei;
            s = (int)p[i];
            d = (int)p[i + N_EDGES];
        } else {
            const int* p = (const int*)ei;
            s = p[i];
            d = p[i + N_EDGES];
        }
        // clamp defensively (reference guarantees in-range)
        s = min(max(s, 0), N_NODES - 1);
        d = min(max(d, 0), N_NODES - 1);
        g_src32[i] = s;
        g_dst32[i] = d;
    }
}

// ---------------------------------------------------------------------------
// K1: in-degree over dst
// ---------------------------------------------------------------------------
__global__ void k_degree() {
    int e = blockIdx.x * blockDim.x + threadIdx.x;
    if (e < N_EDGES) {
        atomicAdd(&g_deg[g_dst32[e]], 1.0f);
    }
}

// ---------------------------------------------------------------------------
// K2: dinv = rsqrt(deg)   (deg >= 1 always)
// ---------------------------------------------------------------------------
__global__ void k_dinv() {
    int i = blockIdx.x * blockDim.x + threadIdx.x;
    if (i < N_NODES) g_dinv[i] = rsqrtf(g_deg[i]);
}

// ---------------------------------------------------------------------------
// K3: h1 = x @ W1   (N x 128) @ (128 x 128), fp32 tiled GEMM
// ---------------------------------------------------------------------------
#define BM 64
#define BN 128
#define BK 16

__global__ __launch_bounds__(256) void k_gemm1(const float* __restrict__ x,
                                               const float* __restrict__ W) {
    __shared__ float As[BK][BM];
    __shared__ float Bs[BK][BN];

    const int tid = threadIdx.x;
    const int blockRow = blockIdx.x * BM;
    const int rtid = tid >> 4;          // 0..15
    const int ctid = tid & 15;          // 0..15
    const int rowBase = rtid * 4;       // 4 rows / thread
    const int colBase = ctid * 8;       // 8 cols / thread

    float acc[4][8];
#pragma unroll
    for (int i = 0; i < 4; i++)
#pragma unroll
        for (int j = 0; j < 8; j++) acc[i][j] = 0.0f;

    for (int k0 = 0; k0 < D_FEAT; k0 += BK) {
        {
            int r  = tid >> 2;              // 0..63
            int kv = (tid & 3) * 4;
            int gr = blockRow + r;
            float4 v = make_float4(0.f, 0.f, 0.f, 0.f);
            if (gr < N_NODES)
                v = *(const float4*)(x + (size_t)gr * D_FEAT + k0 + kv);
            As[kv + 0][r] = v.x;
            As[kv + 1][r] = v.y;
            As[kv + 2][r] = v.z;
            As[kv + 3][r] = v.w;
        }
#pragma unroll
        for (int s = 0; s < 2; s++) {
            int idx = tid + s * 256;        // 0..511
            int k   = idx >> 5;             // 0..15
            int c4  = (idx & 31) * 4;
            *(float4*)(&Bs[k][c4]) = *(const float4*)(W + (size_t)(k0 + k) * HIDDEN + c4);
        }
        __syncthreads();

#pragma unroll
        for (int kk = 0; kk < BK; kk++) {
            float4 av = *(float4*)(&As[kk][rowBase]);
            float a[4] = {av.x, av.y, av.z, av.w};
            float4 b0 = *(float4*)(&Bs[kk][colBase]);
            float4 b1 = *(float4*)(&Bs[kk][colBase + 4]);
            float b[8] = {b0.x, b0.y, b0.z, b0.w, b1.x, b1.y, b1.z, b1.w};
#pragma unroll
            for (int i = 0; i < 4; i++)
#pragma unroll
                for (int j = 0; j < 8; j++)
                    acc[i][j] = fmaf(a[i], b[j], acc[i][j]);
        }
        __syncthreads();
    }

#pragma unroll
    for (int i = 0; i < 4; i++) {
        int gr = blockRow + rowBase + i;
        if (gr < N_NODES) {
            float* dst = g_h1 + (size_t)gr * HIDDEN + colBase;
            *(float4*)(dst + 0) = make_float4(acc[i][0], acc[i][1], acc[i][2], acc[i][3]);
            *(float4*)(dst + 4) = make_float4(acc[i][4], acc[i][5], acc[i][6], acc[i][7]);
        }
    }
}

// ---------------------------------------------------------------------------
// K4: layer-1 edge scatter. One warp per edge; lane handles 4 floats
//     via 4 scalar atomicAdds. agg[dst] += h1[src] * dinv[src]*dinv[dst]
// ---------------------------------------------------------------------------
__global__ __launch_bounds__(256) void k_scatter1() {
    int warp = (blockIdx.x * blockDim.x + threadIdx.x) >> 5;
    int lane = threadIdx.x & 31;
    if (warp >= N_EDGES) return;

    int src = g_src32[warp];
    int dst = g_dst32[warp];
    float norm = g_dinv[src] * g_dinv[dst];

    const float4 v = *(const float4*)(g_h1 + (size_t)src * HIDDEN + lane * 4);
    float* p = g_agg + (size_t)dst * HIDDEN + lane * 4;
    atomicAdd(p + 0, v.x * norm);
    atomicAdd(p + 1, v.y * norm);
    atomicAdd(p + 2, v.z * norm);
    atomicAdd(p + 3, v.w * norm);
}

// ---------------------------------------------------------------------------
// K5: per-node fused: self-loop add, +b1, ReLU, dot with W2, write
//     h2[i] and d_out[i] = h2[i]*dinv[i]^2 + b2. One warp per node.
// ---------------------------------------------------------------------------
__global__ __launch_bounds__(256) void k_relu_lin2(const float* __restrict__ b1,
                                                   const float* __restrict__ W2,
                                                   const float* __restrict__ b2,
                                                   float* __restrict__ out) {
    int node = (blockIdx.x * blockDim.x + threadIdx.x) >> 5;
    int lane = threadIdx.x & 31;
    if (node >= N_NODES) return;

    float di = g_dinv[node];
    float d2 = di * di;
    size_t base = (size_t)node * HIDDEN + lane * 4;

    float4 a  = *(const float4*)(g_agg + base);
    float4 h  = *(const float4*)(g_h1 + base);
    float4 bb = *(const float4*)(b1 + lane * 4);
    float4 w  = *(const float4*)(W2 + lane * 4);

    float t0 = fmaxf(fmaf(h.x, d2, a.x) + bb.x, 0.0f);
    float t1 = fmaxf(fmaf(h.y, d2, a.y) + bb.y, 0.0f);
    float t2 = fmaxf(fmaf(h.z, d2, a.z) + bb.z, 0.0f);
    float t3 = fmaxf(fmaf(h.w, d2, a.w) + bb.w, 0.0f);

    float sum = t0 * w.x + t1 * w.y + t2 * w.z + t3 * w.w;
#pragma unroll
    for (int off = 16; off > 0; off >>= 1)
        sum += __shfl_xor_sync(0xFFFFFFFFu, sum, off);

    if (lane == 0) {
        g_h2[node] = sum;                  // for edge scatter
        out[node]  = fmaf(sum, d2, b2[0]); // self-loop contribution + bias
    }
}

// ---------------------------------------------------------------------------
// K6: layer-2 edge scatter (scalar): out[dst] += h2[src]*dinv[src]*dinv[dst]
// ---------------------------------------------------------------------------
__global__ void k_scatter2(float* __restrict__ out) {
    int e = blockIdx.x * blockDim.x + threadIdx.x;
    if (e < N_EDGES) {
        int src = g_src32[e];
        int dst = g_dst32[e];
        atomicAdd(&out[dst], g_h2[src] * g_dinv[src] * g_dinv[dst]);
    }
}

// ---------------------------------------------------------------------------
// Launch
// Inputs (metadata order): x[N*128] f32, edge_index[2*E] (int32 under default
// JAX x64-disabled; probed at runtime), W1[128*128] f32, b1[128] f32,
// W2[128] f32, b2[1] f32.  Output: [N] f32
// ---------------------------------------------------------------------------
extern "C" void kernel_launch(void* const* d_in, const int* in_sizes, int n_in,
                              void* d_out, int out_size) {
    const float* x    = (const float*)d_in[0];
    const void*  ei   = d_in[1];
    const float* W1   = (const float*)d_in[2];
    const float* b1   = (const float*)d_in[3];
    const float* W2   = (const float*)d_in[4];
    const float* b2   = (const float*)d_in[5];
    float*       out  = (float*)d_out;

    const int T = 256;

    // K_probe: edge dtype detection (1 thread)
    k_probe<<<1, 1>>>(ei);
    // K0: init (agg zero, deg=1, edge int32 conversion)
    {
        int tot = N_NODES * HIDDEN;
        k_init<<<(tot + T - 1) / T, T>>>(ei);
    }
    // K1: degree
    k_degree<<<(N_EDGES + T - 1) / T, T>>>();
    // K2: dinv
    k_dinv<<<(N_NODES + T - 1) / T, T>>>();
    // K3: h1 = x @ W1
    k_gemm1<<<(N_NODES + BM - 1) / BM, 256>>>(x, W1);
    // K4: layer-1 scatter (warp per edge)
    {
        long long warps = N_EDGES;
        long long blocks = (warps * 32 + T - 1) / T;
        k_scatter1<<<(unsigned)blocks, T>>>();
    }
    // K5: fused relu + layer-2 linear + self-loop + bias (warp per node)
    {
        long long warps = N_NODES;
        long long blocks = (warps * 32 + T - 1) / T;
        k_relu_lin2<<<(unsigned)blocks, T>>>(b1, W2, b2, out);
    }
    // K6: layer-2 scatter
    k_scatter2<<<(N_EDGES + T - 1) / T, T>>>(out);
}

// round 4
// speedup vs baseline: 2.1633x; 2.1633x over previous
#include <cuda_runtime.h>
#include <cuda_bf16.h>
#include <stdint.h>

// Problem constants (fixed by the dataset)
#define N_NODES 50000
#define N_EDGES 800000
#define D_FEAT  128
#define HIDDEN  128

#define SCAN_T   256
#define SCAN_B   ((N_NODES + SCAN_T - 1) / SCAN_T)   // 196

// Scratch (static device globals — no allocation allowed)
__device__ float g_dinv[N_NODES];
__device__ float g_h1  [(size_t)N_NODES * HIDDEN];   // x @ W1
__device__ float g_h2  [N_NODES];                    // relu(.) @ W2 per node
__device__ int   g_src32[N_EDGES];
__device__ int   g_dst32[N_EDGES];
__device__ int   g_cnt   [N_NODES];                  // in-degree (no self loop)
__device__ int   g_cursor[N_NODES];                  // fill cursors
__device__ int   g_row   [N_NODES];                  // CSR row starts (exclusive scan)
__device__ int   g_bsum  [SCAN_B];                   // per-block partial sums
__device__ int   g_csr_src [N_EDGES];                // CSR: src per slot
__device__ float g_csr_norm[N_EDGES];                // CSR: dinv[src]*dinv[dst]
__device__ int   g_is64;

// ---------------------------------------------------------------------------
// K_probe: int64 vs int32 edge dtype (JAX x64-disabled downgrades to int32)
// ---------------------------------------------------------------------------
__global__ void k_probe(const void* __restrict__ ei) {
    const long long* p = (const long long*)ei;
    int ok64 = 1;
    for (int i = 0; i < 16; i++) {
        long long v = p[i];
        if (v < 0 || v >= N_NODES) { ok64 = 0; break; }
    }
    g_is64 = ok64;
}

// ---------------------------------------------------------------------------
// K0: convert edges to int32, zero counters
// ---------------------------------------------------------------------------
__global__ void k_init(const void* __restrict__ ei) {
    int i = blockIdx.x * blockDim.x + threadIdx.x;
    if (i < N_NODES) { g_cnt[i] = 0; g_cursor[i] = 0; }
    if (i < N_EDGES) {
        int s, d;
        if (g_is64) {
            const long long* p = (const long long*)ei;
            s = (int)p[i];
            d = (int)p[i + N_EDGES];
        } else {
            const int* p = (const int*)ei;
            s = p[i];
            d = p[i + N_EDGES];
        }
        s = min(max(s, 0), N_NODES - 1);
        d = min(max(d, 0), N_NODES - 1);
        g_src32[i] = s;
        g_dst32[i] = d;
    }
}

// ---------------------------------------------------------------------------
// K1: in-degree counts (int atomics)
// ---------------------------------------------------------------------------
__global__ void k_count() {
    int e = blockIdx.x * blockDim.x + threadIdx.x;
    if (e < N_EDGES) atomicAdd(&g_cnt[g_dst32[e]], 1);
}

// ---------------------------------------------------------------------------
// K2: dinv = rsqrt(1 + cnt)  (self loop included in degree)
// ---------------------------------------------------------------------------
__global__ void k_dinv() {
    int i = blockIdx.x * blockDim.x + threadIdx.x;
    if (i < N_NODES) g_dinv[i] = rsqrtf((float)(1 + g_cnt[i]));
}

// ---------------------------------------------------------------------------
// Scan step 1: per-block sums of g_cnt
// ---------------------------------------------------------------------------
__global__ void k_scan1() {
    __shared__ int sh[SCAN_T];
    int i = blockIdx.x * SCAN_T + threadIdx.x;
    sh[threadIdx.x] = (i < N_NODES) ? g_cnt[i] : 0;
    __syncthreads();
    for (int s = SCAN_T / 2; s > 0; s >>= 1) {
        if (threadIdx.x < s) sh[threadIdx.x] += sh[threadIdx.x + s];
        __syncthreads();
    }
    if (threadIdx.x == 0) g_bsum[blockIdx.x] = sh[0];
}

// ---------------------------------------------------------------------------
// Scan step 2: sequential exclusive scan of 196 block sums (1 thread)
// ---------------------------------------------------------------------------
__global__ void k_scan2() {
    int acc = 0;
    for (int b = 0; b < SCAN_B; b++) {
        int v = g_bsum[b];
        g_bsum[b] = acc;
        acc += v;
    }
}

// ---------------------------------------------------------------------------
// Scan step 3: per-block exclusive scan + block offset -> g_row
// ---------------------------------------------------------------------------
__global__ void k_scan3() {
    __shared__ int sh[SCAN_T];
    int i = blockIdx.x * SCAN_T + threadIdx.x;
    int v = (i < N_NODES) ? g_cnt[i] : 0;
    sh[threadIdx.x] = v;
    __syncthreads();
    // Hillis-Steele inclusive scan
    for (int off = 1; off < SCAN_T; off <<= 1) {
        int t = (threadIdx.x >= off) ? sh[threadIdx.x - off] : 0;
        __syncthreads();
        sh[threadIdx.x] += t;
        __syncthreads();
    }
    if (i < N_NODES)
        g_row[i] = g_bsum[blockIdx.x] + sh[threadIdx.x] - v;  // exclusive
}

// ---------------------------------------------------------------------------
// K_fill: place edges into CSR slots with precomputed norms
// ---------------------------------------------------------------------------
__global__ void k_fill() {
    int e = blockIdx.x * blockDim.x + threadIdx.x;
    if (e < N_EDGES) {
        int src = g_src32[e];
        int dst = g_dst32[e];
        int pos = atomicAdd(&g_cursor[dst], 1);
        int slot = g_row[dst] + pos;
        g_csr_src[slot]  = src;
        g_csr_norm[slot] = g_dinv[src] * g_dinv[dst];
    }
}

// ---------------------------------------------------------------------------
// K3: h1 = x @ W1   (N x 128) @ (128 x 128), fp32 tiled GEMM
// ---------------------------------------------------------------------------
#define BM 64
#define BN 128
#define BK 16

__global__ __launch_bounds__(256) void k_gemm1(const float* __restrict__ x,
                                               const float* __restrict__ W) {
    __shared__ float As[BK][BM];
    __shared__ float Bs[BK][BN];

    const int tid = threadIdx.x;
    const int blockRow = blockIdx.x * BM;
    const int rtid = tid >> 4;
    const int ctid = tid & 15;
    const int rowBase = rtid * 4;
    const int colBase = ctid * 8;

    float acc[4][8];
#pragma unroll
    for (int i = 0; i < 4; i++)
#pragma unroll
        for (int j = 0; j < 8; j++) acc[i][j] = 0.0f;

    for (int k0 = 0; k0 < D_FEAT; k0 += BK) {
        {
            int r  = tid >> 2;
            int kv = (tid & 3) * 4;
            int gr = blockRow + r;
            float4 v = make_float4(0.f, 0.f, 0.f, 0.f);
            if (gr < N_NODES)
                v = *(const float4*)(x + (size_t)gr * D_FEAT + k0 + kv);
            As[kv + 0][r] = v.x;
            As[kv + 1][r] = v.y;
            As[kv + 2][r] = v.z;
            As[kv + 3][r] = v.w;
        }
#pragma unroll
        for (int s = 0; s < 2; s++) {
            int idx = tid + s * 256;
            int k   = idx >> 5;
            int c4  = (idx & 31) * 4;
            *(float4*)(&Bs[k][c4]) = *(const float4*)(W + (size_t)(k0 + k) * HIDDEN + c4);
        }
        __syncthreads();

#pragma unroll
        for (int kk = 0; kk < BK; kk++) {
            float4 av = *(float4*)(&As[kk][rowBase]);
            float a[4] = {av.x, av.y, av.z, av.w};
            float4 b0 = *(float4*)(&Bs[kk][colBase]);
            float4 b1 = *(float4*)(&Bs[kk][colBase + 4]);
            float b[8] = {b0.x, b0.y, b0.z, b0.w, b1.x, b1.y, b1.z, b1.w};
#pragma unroll
            for (int i = 0; i < 4; i++)
#pragma unroll
                for (int j = 0; j < 8; j++)
                    acc[i][j] = fmaf(a[i], b[j], acc[i][j]);
        }
        __syncthreads();
    }

#pragma unroll
    for (int i = 0; i < 4; i++) {
        int gr = blockRow + rowBase + i;
        if (gr < N_NODES) {
            float* dst = g_h1 + (size_t)gr * HIDDEN + colBase;
            *(float4*)(dst + 0) = make_float4(acc[i][0], acc[i][1], acc[i][2], acc[i][3]);
            *(float4*)(dst + 4) = make_float4(acc[i][4], acc[i][5], acc[i][6], acc[i][7]);
        }
    }
}

// ---------------------------------------------------------------------------
// K_agg1: fused layer-1 aggregation + epilogue. One warp per node.
//   acc = sum_in-edges h1[src]*norm  (register accumulation, no atomics)
//   acc += h1[node]*dinv^2  (self loop); +b1; relu; h2 = dot(acc, W2)
//   out[node] = h2*dinv^2 + b2  (self-loop term of layer 2)
// ---------------------------------------------------------------------------
__global__ __launch_bounds__(256) void k_agg1(const float* __restrict__ b1,
                                              const float* __restrict__ W2,
                                              const float* __restrict__ b2,
                                              float* __restrict__ out) {
    int node = (blockIdx.x * blockDim.x + threadIdx.x) >> 5;
    int lane = threadIdx.x & 31;
    if (node >= N_NODES) return;

    int beg = g_row[node];
    int end = beg + g_cnt[node];

    float a0 = 0.f, a1 = 0.f, a2 = 0.f, a3 = 0.f;

    int i = beg;
    for (; i + 1 < end; i += 2) {
        int   s0 = g_csr_src[i];
        int   s1 = g_csr_src[i + 1];
        float n0 = g_csr_norm[i];
        float n1 = g_csr_norm[i + 1];
        float4 v0 = *(const float4*)(g_h1 + (size_t)s0 * HIDDEN + lane * 4);
        float4 v1 = *(const float4*)(g_h1 + (size_t)s1 * HIDDEN + lane * 4);
        a0 = fmaf(v0.x, n0, a0); a1 = fmaf(v0.y, n0, a1);
        a2 = fmaf(v0.z, n0, a2); a3 = fmaf(v0.w, n0, a3);
        a0 = fmaf(v1.x, n1, a0); a1 = fmaf(v1.y, n1, a1);
        a2 = fmaf(v1.z, n1, a2); a3 = fmaf(v1.w, n1, a3);
    }
    if (i < end) {
        int   s0 = g_csr_src[i];
        float n0 = g_csr_norm[i];
        float4 v0 = *(const float4*)(g_h1 + (size_t)s0 * HIDDEN + lane * 4);
        a0 = fmaf(v0.x, n0, a0); a1 = fmaf(v0.y, n0, a1);
        a2 = fmaf(v0.z, n0, a2); a3 = fmaf(v0.w, n0, a3);
    }

    float di = g_dinv[node];
    float d2 = di * di;

    float4 hs = *(const float4*)(g_h1 + (size_t)node * HIDDEN + lane * 4);
    float4 bb = *(const float4*)(b1 + lane * 4);
    float4 w  = *(const float4*)(W2 + lane * 4);

    float t0 = fmaxf(fmaf(hs.x, d2, a0) + bb.x, 0.0f);
    float t1 = fmaxf(fmaf(hs.y, d2, a1) + bb.y, 0.0f);
    float t2 = fmaxf(fmaf(hs.z, d2, a2) + bb.z, 0.0f);
    float t3 = fmaxf(fmaf(hs.w, d2, a3) + bb.w, 0.0f);

    float sum = t0 * w.x + t1 * w.y + t2 * w.z + t3 * w.w;
#pragma unroll
    for (int off = 16; off > 0; off >>= 1)
        sum += __shfl_xor_sync(0xFFFFFFFFu, sum, off);

    if (lane == 0) {
        g_h2[node] = sum;
        out[node]  = fmaf(sum, d2, b2[0]);  // layer-2 self-loop + bias
    }
}

// ---------------------------------------------------------------------------
// K_agg2: layer-2 gather-side aggregation. One warp per node; lanes stride
//   over in-edges. out[node] += sum h2[src]*norm   (no atomics, warp owns node)
// ---------------------------------------------------------------------------
__global__ __launch_bounds__(256) void k_agg2(float* __restrict__ out) {
    int node = (blockIdx.x * blockDim.x + threadIdx.x) >> 5;
    int lane = threadIdx.x & 31;
    if (node >= N_NODES) return;

    int beg = g_row[node];
    int end = beg + g_cnt[node];

    float sum = 0.f;
    for (int i = beg + lane; i < end; i += 32)
        sum = fmaf(g_h2[g_csr_src[i]], g_csr_norm[i], sum);

#pragma unroll
    for (int off = 16; off > 0; off >>= 1)
        sum += __shfl_xor_sync(0xFFFFFFFFu, sum, off);

    if (lane == 0) out[node] += sum;
}

// ---------------------------------------------------------------------------
// Launch
// ---------------------------------------------------------------------------
extern "C" void kernel_launch(void* const* d_in, const int* in_sizes, int n_in,
                              void* d_out, int out_size) {
    const float* x  = (const float*)d_in[0];
    const void*  ei = d_in[1];
    const float* W1 = (const float*)d_in[2];
    const float* b1 = (const float*)d_in[3];
    const float* W2 = (const float*)d_in[4];
    const float* b2 = (const float*)d_in[5];
    float*       out = (float*)d_out;

    const int T = 256;

    k_probe<<<1, 1>>>(ei);
    k_init <<<(N_EDGES + T - 1) / T, T>>>(ei);
    k_count<<<(N_EDGES + T - 1) / T, T>>>();
    k_dinv <<<(N_NODES + T - 1) / T, T>>>();
    k_scan1<<<SCAN_B, SCAN_T>>>();
    k_scan2<<<1, 1>>>();
    k_scan3<<<SCAN_B, SCAN_T>>>();
    k_fill <<<(N_EDGES + T - 1) / T, T>>>();
    k_gemm1<<<(N_NODES + BM - 1) / BM, 256>>>(x, W1);
    {
        long long blocks = ((long long)N_NODES * 32 + T - 1) / T;
        k_agg1<<<(unsigned)blocks, T>>>(b1, W2, b2, out);
        k_agg2<<<(unsigned)blocks, T>>>(out);
    }
}

// round 5
// speedup vs baseline: 2.2476x; 1.0390x over previous
#include <cuda_runtime.h>
#include <cuda_bf16.h>
#include <stdint.h>

// Problem constants (fixed by the dataset)
#define N_NODES 50000
#define N_EDGES 800000
#define D_FEAT  128
#define HIDDEN  128

#define SCAN_T   256
#define SCAN_B   ((N_NODES + SCAN_T - 1) / SCAN_T)   // 196

// Scratch (static device globals — no allocation allowed)
__device__ float g_dinv[N_NODES];
__device__ float g_h1  [(size_t)N_NODES * HIDDEN];   // x @ W1
__device__ float g_h2  [N_NODES];                    // relu(.) @ W2 per node
__device__ int   g_src32[N_EDGES];
__device__ int   g_dst32[N_EDGES];
__device__ int   g_cnt   [N_NODES];                  // in-degree (no self loop)
__device__ int   g_cursor[N_NODES];
__device__ int   g_row   [N_NODES];                  // CSR row starts
__device__ int   g_bsum  [SCAN_B];
__device__ int2  g_csr   [N_EDGES];                  // packed {src, norm-bits}
__device__ int   g_is64;

// ---------------------------------------------------------------------------
// K_prep: zero counters everywhere; global thread 0 probes edge dtype.
// (int32 data read as int64 merges two random indices -> out of range)
// ---------------------------------------------------------------------------
__global__ void k_prep(const void* __restrict__ ei) {
    int i = blockIdx.x * blockDim.x + threadIdx.x;
    if (i < N_NODES) { g_cnt[i] = 0; g_cursor[i] = 0; }
    if (i == 0) {
        const long long* p = (const long long*)ei;
        int ok64 = 1;
        for (int k = 0; k < 16; k++) {
            long long v = p[k];
            if (v < 0 || v >= N_NODES) { ok64 = 0; break; }
        }
        g_is64 = ok64;
    }
}

// ---------------------------------------------------------------------------
// K_init: convert edges to int32 AND count in-degrees (fused)
// ---------------------------------------------------------------------------
__global__ void k_init(const void* __restrict__ ei) {
    int i = blockIdx.x * blockDim.x + threadIdx.x;
    if (i < N_EDGES) {
        int s, d;
        if (g_is64) {
            const long long* p = (const long long*)ei;
            s = (int)p[i];
            d = (int)p[i + N_EDGES];
        } else {
            const int* p = (const int*)ei;
            s = p[i];
            d = p[i + N_EDGES];
        }
        s = min(max(s, 0), N_NODES - 1);
        d = min(max(d, 0), N_NODES - 1);
        g_src32[i] = s;
        g_dst32[i] = d;
        atomicAdd(&g_cnt[d], 1);
    }
}

// ---------------------------------------------------------------------------
// Scan step 1: per-block sums of g_cnt; also dinv = rsqrt(1+cnt) (fused)
// ---------------------------------------------------------------------------
__global__ void k_scan1() {
    __shared__ int sh[SCAN_T];
    int i = blockIdx.x * SCAN_T + threadIdx.x;
    int c = (i < N_NODES) ? g_cnt[i] : 0;
    if (i < N_NODES) g_dinv[i] = rsqrtf((float)(1 + c));
    sh[threadIdx.x] = c;
    __syncthreads();
    for (int s = SCAN_T / 2; s > 0; s >>= 1) {
        if (threadIdx.x < s) sh[threadIdx.x] += sh[threadIdx.x + s];
        __syncthreads();
    }
    if (threadIdx.x == 0) g_bsum[blockIdx.x] = sh[0];
}

// ---------------------------------------------------------------------------
// Scan step 2: sequential exclusive scan of 196 block sums (1 thread)
// ---------------------------------------------------------------------------
__global__ void k_scan2() {
    int acc = 0;
    for (int b = 0; b < SCAN_B; b++) {
        int v = g_bsum[b];
        g_bsum[b] = acc;
        acc += v;
    }
}

// ---------------------------------------------------------------------------
// Scan step 3: per-block exclusive scan + block offset -> g_row
// ---------------------------------------------------------------------------
__global__ void k_scan3() {
    __shared__ int sh[SCAN_T];
    int i = blockIdx.x * SCAN_T + threadIdx.x;
    int v = (i < N_NODES) ? g_cnt[i] : 0;
    sh[threadIdx.x] = v;
    __syncthreads();
    for (int off = 1; off < SCAN_T; off <<= 1) {
        int t = (threadIdx.x >= off) ? sh[threadIdx.x - off] : 0;
        __syncthreads();
        sh[threadIdx.x] += t;
        __syncthreads();
    }
    if (i < N_NODES)
        g_row[i] = g_bsum[blockIdx.x] + sh[threadIdx.x] - v;  // exclusive
}

// ---------------------------------------------------------------------------
// K_fill: place edges into CSR slots; packed {src, norm}
// ---------------------------------------------------------------------------
__global__ void k_fill() {
    int e = blockIdx.x * blockDim.x + threadIdx.x;
    if (e < N_EDGES) {
        int src = g_src32[e];
        int dst = g_dst32[e];
        int pos = atomicAdd(&g_cursor[dst], 1);
        float norm = g_dinv[src] * g_dinv[dst];
        g_csr[g_row[dst] + pos] = make_int2(src, __float_as_int(norm));
    }
}

// ---------------------------------------------------------------------------
// K3: h1 = x @ W1.  BM=128, BN=128, BK=8, 256 threads, 8x8 per-thread tile.
// ---------------------------------------------------------------------------
#define BM 128
#define BN 128
#define BK 8

__global__ __launch_bounds__(256) void k_gemm1(const float* __restrict__ x,
                                               const float* __restrict__ W) {
    __shared__ float As[BK][BM];
    __shared__ float Bs[BK][BN];

    const int tid = threadIdx.x;
    const int blockRow = blockIdx.x * BM;
    const int rowBase = (tid >> 4) * 8;   // 0..120
    const int colBase = (tid & 15) * 8;   // 0..120

    float acc[8][8];
#pragma unroll
    for (int i = 0; i < 8; i++)
#pragma unroll
        for (int j = 0; j < 8; j++) acc[i][j] = 0.0f;

    for (int k0 = 0; k0 < D_FEAT; k0 += BK) {
        // A tile: 128 rows x 8 k = 256 float4. thread -> row tid>>1, kquad (tid&1)*4
        {
            int r  = tid >> 1;
            int kv = (tid & 1) * 4;
            int gr = blockRow + r;
            float4 v = make_float4(0.f, 0.f, 0.f, 0.f);
            if (gr < N_NODES)
                v = *(const float4*)(x + (size_t)gr * D_FEAT + k0 + kv);
            As[kv + 0][r] = v.x;
            As[kv + 1][r] = v.y;
            As[kv + 2][r] = v.z;
            As[kv + 3][r] = v.w;
        }
        // B tile: 8 k x 128 n = 256 float4. thread -> k tid>>5, c4 (tid&31)*4
        {
            int k  = tid >> 5;
            int c4 = (tid & 31) * 4;
            *(float4*)(&Bs[k][c4]) = *(const float4*)(W + (size_t)(k0 + k) * HIDDEN + c4);
        }
        __syncthreads();

#pragma unroll
        for (int kk = 0; kk < BK; kk++) {
            float4 a0 = *(float4*)(&As[kk][rowBase]);
            float4 a1 = *(float4*)(&As[kk][rowBase + 4]);
            float4 b0 = *(float4*)(&Bs[kk][colBase]);
            float4 b1 = *(float4*)(&Bs[kk][colBase + 4]);
            float a[8] = {a0.x, a0.y, a0.z, a0.w, a1.x, a1.y, a1.z, a1.w};
            float b[8] = {b0.x, b0.y, b0.z, b0.w, b1.x, b1.y, b1.z, b1.w};
#pragma unroll
            for (int i = 0; i < 8; i++)
#pragma unroll
                for (int j = 0; j < 8; j++)
                    acc[i][j] = fmaf(a[i], b[j], acc[i][j]);
        }
        __syncthreads();
    }

#pragma unroll
    for (int i = 0; i < 8; i++) {
        int gr = blockRow + rowBase + i;
        if (gr < N_NODES) {
            float* dst = g_h1 + (size_t)gr * HIDDEN + colBase;
            *(float4*)(dst + 0) = make_float4(acc[i][0], acc[i][1], acc[i][2], acc[i][3]);
            *(float4*)(dst + 4) = make_float4(acc[i][4], acc[i][5], acc[i][6], acc[i][7]);
        }
    }
}

// ---------------------------------------------------------------------------
// K_agg1: fused layer-1 aggregation + epilogue. One warp per node.
// ---------------------------------------------------------------------------
__global__ __launch_bounds__(256) void k_agg1(const float* __restrict__ b1,
                                              const float* __restrict__ W2,
                                              const float* __restrict__ b2,
                                              float* __restrict__ out) {
    int node = (blockIdx.x * blockDim.x + threadIdx.x) >> 5;
    int lane = threadIdx.x & 31;
    if (node >= N_NODES) return;

    int beg = g_row[node];
    int end = beg + g_cnt[node];

    float a0 = 0.f, a1 = 0.f, a2 = 0.f, a3 = 0.f;

    int i = beg;
    for (; i + 3 < end; i += 4) {
        int2 e0 = g_csr[i];
        int2 e1 = g_csr[i + 1];
        int2 e2 = g_csr[i + 2];
        int2 e3 = g_csr[i + 3];
        float4 v0 = *(const float4*)(g_h1 + (size_t)e0.x * HIDDEN + lane * 4);
        float4 v1 = *(const float4*)(g_h1 + (size_t)e1.x * HIDDEN + lane * 4);
        float4 v2 = *(const float4*)(g_h1 + (size_t)e2.x * HIDDEN + lane * 4);
        float4 v3 = *(const float4*)(g_h1 + (size_t)e3.x * HIDDEN + lane * 4);
        float n0 = __int_as_float(e0.y), n1 = __int_as_float(e1.y);
        float n2 = __int_as_float(e2.y), n3 = __int_as_float(e3.y);
        a0 = fmaf(v0.x, n0, a0); a1 = fmaf(v0.y, n0, a1);
        a2 = fmaf(v0.z, n0, a2); a3 = fmaf(v0.w, n0, a3);
        a0 = fmaf(v1.x, n1, a0); a1 = fmaf(v1.y, n1, a1);
        a2 = fmaf(v1.z, n1, a2); a3 = fmaf(v1.w, n1, a3);
        a0 = fmaf(v2.x, n2, a0); a1 = fmaf(v2.y, n2, a1);
        a2 = fmaf(v2.z, n2, a2); a3 = fmaf(v2.w, n2, a3);
        a0 = fmaf(v3.x, n3, a0); a1 = fmaf(v3.y, n3, a1);
        a2 = fmaf(v3.z, n3, a2); a3 = fmaf(v3.w, n3, a3);
    }
    for (; i < end; i++) {
        int2 e0 = g_csr[i];
        float n0 = __int_as_float(e0.y);
        float4 v0 = *(const float4*)(g_h1 + (size_t)e0.x * HIDDEN + lane * 4);
        a0 = fmaf(v0.x, n0, a0); a1 = fmaf(v0.y, n0, a1);
        a2 = fmaf(v0.z, n0, a2); a3 = fmaf(v0.w, n0, a3);
    }

    float di = g_dinv[node];
    float d2 = di * di;

    float4 hs = *(const float4*)(g_h1 + (size_t)node * HIDDEN + lane * 4);
    float4 bb = *(const float4*)(b1 + lane * 4);
    float4 w  = *(const float4*)(W2 + lane * 4);

    float t0 = fmaxf(fmaf(hs.x, d2, a0) + bb.x, 0.0f);
    float t1 = fmaxf(fmaf(hs.y, d2, a1) + bb.y, 0.0f);
    float t2 = fmaxf(fmaf(hs.z, d2, a2) + bb.z, 0.0f);
    float t3 = fmaxf(fmaf(hs.w, d2, a3) + bb.w, 0.0f);

    float sum = t0 * w.x + t1 * w.y + t2 * w.z + t3 * w.w;
#pragma unroll
    for (int off = 16; off > 0; off >>= 1)
        sum += __shfl_xor_sync(0xFFFFFFFFu, sum, off);

    if (lane == 0) {
        g_h2[node] = sum;
        out[node]  = fmaf(sum, d2, b2[0]);  // layer-2 self-loop + bias
    }
}

// ---------------------------------------------------------------------------
// K_agg2: layer-2 gather. One warp per node; lanes stride over in-edges.
// ---------------------------------------------------------------------------
__global__ __launch_bounds__(256) void k_agg2(float* __restrict__ out) {
    int node = (blockIdx.x * blockDim.x + threadIdx.x) >> 5;
    int lane = threadIdx.x & 31;
    if (node >= N_NODES) return;

    int beg = g_row[node];
    int end = beg + g_cnt[node];

    float sum = 0.f;
    for (int i = beg + lane; i < end; i += 32) {
        int2 e = g_csr[i];
        sum = fmaf(g_h2[e.x], __int_as_float(e.y), sum);
    }

#pragma unroll
    for (int off = 16; off > 0; off >>= 1)
        sum += __shfl_xor_sync(0xFFFFFFFFu, sum, off);

    if (lane == 0) out[node] += sum;
}

// ---------------------------------------------------------------------------
// Launch
// ---------------------------------------------------------------------------
extern "C" void kernel_launch(void* const* d_in, const int* in_sizes, int n_in,
                              void* d_out, int out_size) {
    const float* x  = (const float*)d_in[0];
    const void*  ei = d_in[1];
    const float* W1 = (const float*)d_in[2];
    const float* b1 = (const float*)d_in[3];
    const float* W2 = (const float*)d_in[4];
    const float* b2 = (const float*)d_in[5];
    float*       out = (float*)d_out;

    const int T = 256;

    k_prep <<<(N_NODES + T - 1) / T, T>>>(ei);
    k_init <<<(N_EDGES + T - 1) / T, T>>>(ei);
    k_scan1<<<SCAN_B, SCAN_T>>>();
    k_scan2<<<1, 1>>>();
    k_scan3<<<SCAN_B, SCAN_T>>>();
    k_fill <<<(N_EDGES + T - 1) / T, T>>>();
    k_gemm1<<<(N_NODES + BM - 1) / BM, 256>>>(x, W1);
    {
        long long blocks = ((long long)N_NODES * 32 + T - 1) / T;
        k_agg1<<<(unsigned)blocks, T>>>(b1, W2, b2, out);
        k_agg2<<<(unsigned)blocks, T>>>(out);
    }
}

// round 6
// speedup vs baseline: 2.6870x; 1.1955x over previous
#include <cuda_runtime.h>
#include <cuda_fp16.h>
#include <stdint.h>

// Problem constants (fixed by the dataset)
#define N_NODES 50000
#define N_EDGES 800000
#define D_FEAT  128
#define HIDDEN  128

#define SCAN_T   256
#define SCAN_B   ((N_NODES + SCAN_T - 1) / SCAN_T)   // 196

// Scratch (static device globals — no allocation allowed)
__device__ float  g_dinv[N_NODES];
__device__ float  g_h1 [(size_t)N_NODES * HIDDEN];    // x @ W1 (fp32, for self-loop)
__device__ __half g_h1h[(size_t)N_NODES * HIDDEN];    // x @ W1 (fp16, for gathers)
__device__ float  g_h2 [N_NODES];                     // relu(.) @ W2 per node
__device__ int    g_cnt   [N_NODES];                  // in-degree (no self loop)
__device__ int    g_cursor[N_NODES];
__device__ int    g_row   [N_NODES];                  // CSR row starts
__device__ int    g_bsum  [SCAN_B];
__device__ int2   g_csr   [N_EDGES];                  // packed {src, norm-bits}
__device__ int    g_is64;

// ---------------------------------------------------------------------------
// Edge fetch helper (dtype decided by runtime probe)
// ---------------------------------------------------------------------------
__device__ __forceinline__ void load_edge(const void* ei, int i, int& s, int& d) {
    if (g_is64) {
        const long long* p = (const long long*)ei;
        s = (int)p[i];
        d = (int)p[i + N_EDGES];
    } else {
        const int* p = (const int*)ei;
        s = p[i];
        d = p[i + N_EDGES];
    }
    s = min(max(s, 0), N_NODES - 1);
    d = min(max(d, 0), N_NODES - 1);
}

// ---------------------------------------------------------------------------
// K_prep: zero counters; global thread 0 probes edge dtype.
// (int32 data read as int64 merges two random indices -> out of range)
// ---------------------------------------------------------------------------
__global__ void k_prep(const void* __restrict__ ei) {
    int i = blockIdx.x * blockDim.x + threadIdx.x;
    if (i < N_NODES) { g_cnt[i] = 0; g_cursor[i] = 0; }
    if (i == 0) {
        const long long* p = (const long long*)ei;
        int ok64 = 1;
        for (int k = 0; k < 16; k++) {
            long long v = p[k];
            if (v < 0 || v >= N_NODES) { ok64 = 0; break; }
        }
        g_is64 = ok64;
    }
}

// ---------------------------------------------------------------------------
// K_count: in-degree counts straight from edge_index
// ---------------------------------------------------------------------------
__global__ void k_count(const void* __restrict__ ei) {
    int i = blockIdx.x * blockDim.x + threadIdx.x;
    if (i < N_EDGES) {
        int s, d;
        load_edge(ei, i, s, d);
        atomicAdd(&g_cnt[d], 1);
    }
}

// ---------------------------------------------------------------------------
// Scan step 1: per-block sums of g_cnt; also dinv = rsqrt(1+cnt) (fused)
// ---------------------------------------------------------------------------
__global__ void k_scan1() {
    __shared__ int sh[SCAN_T];
    int i = blockIdx.x * SCAN_T + threadIdx.x;
    int c = (i < N_NODES) ? g_cnt[i] : 0;
    if (i < N_NODES) g_dinv[i] = rsqrtf((float)(1 + c));
    sh[threadIdx.x] = c;
    __syncthreads();
    for (int s = SCAN_T / 2; s > 0; s >>= 1) {
        if (threadIdx.x < s) sh[threadIdx.x] += sh[threadIdx.x + s];
        __syncthreads();
    }
    if (threadIdx.x == 0) g_bsum[blockIdx.x] = sh[0];
}

// ---------------------------------------------------------------------------
// Scan step 2 (fused): every block redundantly scans the 196 block sums in
// smem (exclusive prefix for its own blockIdx), then does its local
// 256-element exclusive scan -> g_row. No serial kernel, no extra launch.
// ---------------------------------------------------------------------------
__global__ void k_scan3() {
    __shared__ int shb[SCAN_T];   // block-sum scan
    __shared__ int sh [SCAN_T];   // local scan

    // 1) scan of per-block sums (inclusive), then pick exclusive at blockIdx
    int bv = (threadIdx.x < SCAN_B) ? g_bsum[threadIdx.x] : 0;
    shb[threadIdx.x] = bv;
    __syncthreads();
    for (int off = 1; off < SCAN_T; off <<= 1) {
        int t = (threadIdx.x >= off) ? shb[threadIdx.x - off] : 0;
        __syncthreads();
        shb[threadIdx.x] += t;
        __syncthreads();
    }
    // exclusive prefix for this block = inclusive[blockIdx] - bsum[blockIdx]
    int blockOff = shb[blockIdx.x] - g_bsum[blockIdx.x];

    // 2) local scan over this block's 256 counts
    int i = blockIdx.x * SCAN_T + threadIdx.x;
    int v = (i < N_NODES) ? g_cnt[i] : 0;
    sh[threadIdx.x] = v;
    __syncthreads();
    for (int off = 1; off < SCAN_T; off <<= 1) {
        int t = (threadIdx.x >= off) ? sh[threadIdx.x - off] : 0;
        __syncthreads();
        sh[threadIdx.x] += t;
        __syncthreads();
    }
    if (i < N_NODES)
        g_row[i] = blockOff + sh[threadIdx.x] - v;   // exclusive
}

// ---------------------------------------------------------------------------
// K_fill: place edges into CSR slots; packed {src, norm}
// ---------------------------------------------------------------------------
__global__ void k_fill(const void* __restrict__ ei) {
    int e = blockIdx.x * blockDim.x + threadIdx.x;
    if (e < N_EDGES) {
        int src, dst;
        load_edge(ei, e, src, dst);
        int pos = atomicAdd(&g_cursor[dst], 1);
        float norm = g_dinv[src] * g_dinv[dst];
        g_csr[g_row[dst] + pos] = make_int2(src, __float_as_int(norm));
    }
}

// ---------------------------------------------------------------------------
// K3: h1 = x @ W1.  BM=128, BN=128, BK=8, 256 threads, 8x8 per-thread tile.
// Epilogue writes fp32 (self-loop path) AND fp16 (gather path).
// ---------------------------------------------------------------------------
#define BM 128
#define BN 128
#define BK 8

__global__ __launch_bounds__(256) void k_gemm1(const float* __restrict__ x,
                                               const float* __restrict__ W) {
    __shared__ float As[BK][BM];
    __shared__ float Bs[BK][BN];

    const int tid = threadIdx.x;
    const int blockRow = blockIdx.x * BM;
    const int rowBase = (tid >> 4) * 8;
    const int colBase = (tid & 15) * 8;

    float acc[8][8];
#pragma unroll
    for (int i = 0; i < 8; i++)
#pragma unroll
        for (int j = 0; j < 8; j++) acc[i][j] = 0.0f;

    for (int k0 = 0; k0 < D_FEAT; k0 += BK) {
        {
            int r  = tid >> 1;
            int kv = (tid & 1) * 4;
            int gr = blockRow + r;
            float4 v = make_float4(0.f, 0.f, 0.f, 0.f);
            if (gr < N_NODES)
                v = *(const float4*)(x + (size_t)gr * D_FEAT + k0 + kv);
            As[kv + 0][r] = v.x;
            As[kv + 1][r] = v.y;
            As[kv + 2][r] = v.z;
            As[kv + 3][r] = v.w;
        }
        {
            int k  = tid >> 5;
            int c4 = (tid & 31) * 4;
            *(float4*)(&Bs[k][c4]) = *(const float4*)(W + (size_t)(k0 + k) * HIDDEN + c4);
        }
        __syncthreads();

#pragma unroll
        for (int kk = 0; kk < BK; kk++) {
            float4 a0 = *(float4*)(&As[kk][rowBase]);
            float4 a1 = *(float4*)(&As[kk][rowBase + 4]);
            float4 b0 = *(float4*)(&Bs[kk][colBase]);
            float4 b1 = *(float4*)(&Bs[kk][colBase + 4]);
            float a[8] = {a0.x, a0.y, a0.z, a0.w, a1.x, a1.y, a1.z, a1.w};
            float b[8] = {b0.x, b0.y, b0.z, b0.w, b1.x, b1.y, b1.z, b1.w};
#pragma unroll
            for (int i = 0; i < 8; i++)
#pragma unroll
                for (int j = 0; j < 8; j++)
                    acc[i][j] = fmaf(a[i], b[j], acc[i][j]);
        }
        __syncthreads();
    }

#pragma unroll
    for (int i = 0; i < 8; i++) {
        int gr = blockRow + rowBase + i;
        if (gr < N_NODES) {
            float* dst = g_h1 + (size_t)gr * HIDDEN + colBase;
            *(float4*)(dst + 0) = make_float4(acc[i][0], acc[i][1], acc[i][2], acc[i][3]);
            *(float4*)(dst + 4) = make_float4(acc[i][4], acc[i][5], acc[i][6], acc[i][7]);
            // fp16 copy for the gather path
            __half2 hpack[4];
            hpack[0] = __floats2half2_rn(acc[i][0], acc[i][1]);
            hpack[1] = __floats2half2_rn(acc[i][2], acc[i][3]);
            hpack[2] = __floats2half2_rn(acc[i][4], acc[i][5]);
            hpack[3] = __floats2half2_rn(acc[i][6], acc[i][7]);
            *(uint4*)(g_h1h + (size_t)gr * HIDDEN + colBase) = *(uint4*)hpack;
        }
    }
}

// ---------------------------------------------------------------------------
// K_agg1: fused layer-1 aggregation + epilogue. One warp per node.
// Gathers fp16 rows (256B/edge), accumulates fp32. Self-loop from fp32 h1.
// ---------------------------------------------------------------------------
__global__ __launch_bounds__(256) void k_agg1(const float* __restrict__ b1,
                                              const float* __restrict__ W2,
                                              const float* __restrict__ b2,
                                              float* __restrict__ out) {
    int node = (blockIdx.x * blockDim.x + threadIdx.x) >> 5;
    int lane = threadIdx.x & 31;
    if (node >= N_NODES) return;

    int beg = g_row[node];
    int end = beg + g_cnt[node];

    float a0 = 0.f, a1 = 0.f, a2 = 0.f, a3 = 0.f;

    int i = beg;
    for (; i + 3 < end; i += 4) {
        int2 e0 = g_csr[i];
        int2 e1 = g_csr[i + 1];
        int2 e2 = g_csr[i + 2];
        int2 e3 = g_csr[i + 3];
        uint2 r0 = *(const uint2*)(g_h1h + (size_t)e0.x * HIDDEN + lane * 4);
        uint2 r1 = *(const uint2*)(g_h1h + (size_t)e1.x * HIDDEN + lane * 4);
        uint2 r2 = *(const uint2*)(g_h1h + (size_t)e2.x * HIDDEN + lane * 4);
        uint2 r3 = *(const uint2*)(g_h1h + (size_t)e3.x * HIDDEN + lane * 4);
        float n0 = __int_as_float(e0.y), n1 = __int_as_float(e1.y);
        float n2 = __int_as_float(e2.y), n3 = __int_as_float(e3.y);
        float2 p, q;
        p = __half22float2(*(__half2*)&r0.x); q = __half22float2(*(__half2*)&r0.y);
        a0 = fmaf(p.x, n0, a0); a1 = fmaf(p.y, n0, a1);
        a2 = fmaf(q.x, n0, a2); a3 = fmaf(q.y, n0, a3);
        p = __half22float2(*(__half2*)&r1.x); q = __half22float2(*(__half2*)&r1.y);
        a0 = fmaf(p.x, n1, a0); a1 = fmaf(p.y, n1, a1);
        a2 = fmaf(q.x, n1, a2); a3 = fmaf(q.y, n1, a3);
        p = __half22float2(*(__half2*)&r2.x); q = __half22float2(*(__half2*)&r2.y);
        a0 = fmaf(p.x, n2, a0); a1 = fmaf(p.y, n2, a1);
        a2 = fmaf(q.x, n2, a2); a3 = fmaf(q.y, n2, a3);
        p = __half22float2(*(__half2*)&r3.x); q = __half22float2(*(__half2*)&r3.y);
        a0 = fmaf(p.x, n3, a0); a1 = fmaf(p.y, n3, a1);
        a2 = fmaf(q.x, n3, a2); a3 = fmaf(q.y, n3, a3);
    }
    for (; i < end; i++) {
        int2 e0 = g_csr[i];
        float n0 = __int_as_float(e0.y);
        uint2 r0 = *(const uint2*)(g_h1h + (size_t)e0.x * HIDDEN + lane * 4);
        float2 p = __half22float2(*(__half2*)&r0.x);
        float2 q = __half22float2(*(__half2*)&r0.y);
        a0 = fmaf(p.x, n0, a0); a1 = fmaf(p.y, n0, a1);
        a2 = fmaf(q.x, n0, a2); a3 = fmaf(q.y, n0, a3);
    }

    float di = g_dinv[node];
    float d2 = di * di;

    float4 hs = *(const float4*)(g_h1 + (size_t)node * HIDDEN + lane * 4);
    float4 bb = *(const float4*)(b1 + lane * 4);
    float4 w  = *(const float4*)(W2 + lane * 4);

    float t0 = fmaxf(fmaf(hs.x, d2, a0) + bb.x, 0.0f);
    float t1 = fmaxf(fmaf(hs.y, d2, a1) + bb.y, 0.0f);
    float t2 = fmaxf(fmaf(hs.z, d2, a2) + bb.z, 0.0f);
    float t3 = fmaxf(fmaf(hs.w, d2, a3) + bb.w, 0.0f);

    float sum = t0 * w.x + t1 * w.y + t2 * w.z + t3 * w.w;
#pragma unroll
    for (int off = 16; off > 0; off >>= 1)
        sum += __shfl_xor_sync(0xFFFFFFFFu, sum, off);

    if (lane == 0) {
        g_h2[node] = sum;
        out[node]  = fmaf(sum, d2, b2[0]);  // layer-2 self-loop + bias
    }
}

// ---------------------------------------------------------------------------
// K_agg2: layer-2 gather. One warp per node; lanes stride over in-edges.
// ---------------------------------------------------------------------------
__global__ __launch_bounds__(256) void k_agg2(float* __restrict__ out) {
    int node = (blockIdx.x * blockDim.x + threadIdx.x) >> 5;
    int lane = threadIdx.x & 31;
    if (node >= N_NODES) return;

    int beg = g_row[node];
    int end = beg + g_cnt[node];

    float sum = 0.f;
    for (int i = beg + lane; i < end; i += 32) {
        int2 e = g_csr[i];
        sum = fmaf(g_h2[e.x], __int_as_float(e.y), sum);
    }

#pragma unroll
    for (int off = 16; off > 0; off >>= 1)
        sum += __shfl_xor_sync(0xFFFFFFFFu, sum, off);

    if (lane == 0) out[node] += sum;
}

// ---------------------------------------------------------------------------
// Launch
// ---------------------------------------------------------------------------
extern "C" void kernel_launch(void* const* d_in, const int* in_sizes, int n_in,
                              void* d_out, int out_size) {
    const float* x  = (const float*)d_in[0];
    const void*  ei = d_in[1];
    const float* W1 = (const float*)d_in[2];
    const float* b1 = (const float*)d_in[3];
    const float* W2 = (const float*)d_in[4];
    const float* b2 = (const float*)d_in[5];
    float*       out = (float*)d_out;

    const int T = 256;

    k_prep <<<(N_NODES + T - 1) / T, T>>>(ei);
    k_count<<<(N_EDGES + T - 1) / T, T>>>(ei);
    k_scan1<<<SCAN_B, SCAN_T>>>();
    k_scan3<<<SCAN_B, SCAN_T>>>();
    k_fill <<<(N_EDGES + T - 1) / T, T>>>(ei);
    k_gemm1<<<(N_NODES + BM - 1) / BM, 256>>>(x, W1);
    {
        long long blocks = ((long long)N_NODES * 32 + T - 1) / T;
        k_agg1<<<(unsigned)blocks, T>>>(b1, W2, b2, out);
        k_agg2<<<(unsigned)blocks, T>>>(out);
    }
}

// round 7
// speedup vs baseline: 2.8371x; 1.0558x over previous
#include <cuda_runtime.h>
#include <cuda_fp16.h>
#include <stdint.h>

// Problem constants (fixed by the dataset)
#define N_NODES 50000
#define N_EDGES 800000
#define D_FEAT  128
#define HIDDEN  128

#define SCAN_T   256
#define SCAN_B   ((N_NODES + SCAN_T - 1) / SCAN_T)   // 196

// Scratch (static device globals — no allocation allowed)
__device__ float  g_dinv[N_NODES];
__device__ __half g_h1h[(size_t)N_NODES * HIDDEN];    // x @ W1 (fp16)
__device__ float  g_h2 [N_NODES];                     // relu(.) @ W2 per node
__device__ int    g_cnt   [N_NODES];                  // in-degree (no self loop)
__device__ int    g_cursor[N_NODES];
__device__ int    g_row   [N_NODES];                  // CSR row starts
__device__ int    g_bsum  [SCAN_B];
__device__ int2   g_csr   [N_EDGES];                  // packed {src, norm-bits}
__device__ int    g_is64;

// ---------------------------------------------------------------------------
// Edge fetch helper (dtype decided by runtime probe)
// ---------------------------------------------------------------------------
__device__ __forceinline__ void load_edge(const void* ei, int i, int& s, int& d) {
    if (g_is64) {
        const long long* p = (const long long*)ei;
        s = (int)p[i];
        d = (int)p[i + N_EDGES];
    } else {
        const int* p = (const int*)ei;
        s = p[i];
        d = p[i + N_EDGES];
    }
    s = min(max(s, 0), N_NODES - 1);
    d = min(max(d, 0), N_NODES - 1);
}

// ---------------------------------------------------------------------------
// K_prep: zero counters; global thread 0 probes edge dtype.
// ---------------------------------------------------------------------------
__global__ void k_prep(const void* __restrict__ ei) {
    int i = blockIdx.x * blockDim.x + threadIdx.x;
    if (i < N_NODES) { g_cnt[i] = 0; g_cursor[i] = 0; }
    if (i == 0) {
        const long long* p = (const long long*)ei;
        int ok64 = 1;
        for (int k = 0; k < 16; k++) {
            long long v = p[k];
            if (v < 0 || v >= N_NODES) { ok64 = 0; break; }
        }
        g_is64 = ok64;
    }
}

// ---------------------------------------------------------------------------
// K_count: in-degree counts straight from edge_index
// ---------------------------------------------------------------------------
__global__ void k_count(const void* __restrict__ ei) {
    int i = blockIdx.x * blockDim.x + threadIdx.x;
    if (i < N_EDGES) {
        int s, d;
        load_edge(ei, i, s, d);
        atomicAdd(&g_cnt[d], 1);
    }
}

// ---------------------------------------------------------------------------
// Scan step 1: per-block sums of g_cnt; also dinv = rsqrt(1+cnt) (fused)
// ---------------------------------------------------------------------------
__global__ void k_scan1() {
    __shared__ int sh[SCAN_T];
    int i = blockIdx.x * SCAN_T + threadIdx.x;
    int c = (i < N_NODES) ? g_cnt[i] : 0;
    if (i < N_NODES) g_dinv[i] = rsqrtf((float)(1 + c));
    sh[threadIdx.x] = c;
    __syncthreads();
    for (int s = SCAN_T / 2; s > 0; s >>= 1) {
        if (threadIdx.x < s) sh[threadIdx.x] += sh[threadIdx.x + s];
        __syncthreads();
    }
    if (threadIdx.x == 0) g_bsum[blockIdx.x] = sh[0];
}

// ---------------------------------------------------------------------------
// Scan step 2 (fused): every block redundantly scans the 196 block sums,
// then its local 256-element exclusive scan -> g_row.
// ---------------------------------------------------------------------------
__global__ void k_scan3() {
    __shared__ int shb[SCAN_T];
    __shared__ int sh [SCAN_T];

    int bv = (threadIdx.x < SCAN_B) ? g_bsum[threadIdx.x] : 0;
    shb[threadIdx.x] = bv;
    __syncthreads();
    for (int off = 1; off < SCAN_T; off <<= 1) {
        int t = (threadIdx.x >= off) ? shb[threadIdx.x - off] : 0;
        __syncthreads();
        shb[threadIdx.x] += t;
        __syncthreads();
    }
    int blockOff = shb[blockIdx.x] - g_bsum[blockIdx.x];

    int i = blockIdx.x * SCAN_T + threadIdx.x;
    int v = (i < N_NODES) ? g_cnt[i] : 0;
    sh[threadIdx.x] = v;
    __syncthreads();
    for (int off = 1; off < SCAN_T; off <<= 1) {
        int t = (threadIdx.x >= off) ? sh[threadIdx.x - off] : 0;
        __syncthreads();
        sh[threadIdx.x] += t;
        __syncthreads();
    }
    if (i < N_NODES)
        g_row[i] = blockOff + sh[threadIdx.x] - v;
}

// ---------------------------------------------------------------------------
// K_fill: place edges into CSR slots; packed {src, norm}
// ---------------------------------------------------------------------------
__global__ void k_fill(const void* __restrict__ ei) {
    int e = blockIdx.x * blockDim.x + threadIdx.x;
    if (e < N_EDGES) {
        int src, dst;
        load_edge(ei, e, src, dst);
        int pos = atomicAdd(&g_cursor[dst], 1);
        float norm = g_dinv[src] * g_dinv[dst];
        g_csr[g_row[dst] + pos] = make_int2(src, __float_as_int(norm));
    }
}

// ---------------------------------------------------------------------------
// K3: h1 = x @ W1.  BM=128, BN=128, BK=8, 256 threads, 8x8 per-thread tile.
// Epilogue writes fp16 only.
// ---------------------------------------------------------------------------
#define BM 128
#define BN 128
#define BK 8

__global__ __launch_bounds__(256) void k_gemm1(const float* __restrict__ x,
                                               const float* __restrict__ W) {
    __shared__ float As[BK][BM];
    __shared__ float Bs[BK][BN];

    const int tid = threadIdx.x;
    const int blockRow = blockIdx.x * BM;
    const int rowBase = (tid >> 4) * 8;
    const int colBase = (tid & 15) * 8;

    float acc[8][8];
#pragma unroll
    for (int i = 0; i < 8; i++)
#pragma unroll
        for (int j = 0; j < 8; j++) acc[i][j] = 0.0f;

    for (int k0 = 0; k0 < D_FEAT; k0 += BK) {
        {
            int r  = tid >> 1;
            int kv = (tid & 1) * 4;
            int gr = blockRow + r;
            float4 v = make_float4(0.f, 0.f, 0.f, 0.f);
            if (gr < N_NODES)
                v = *(const float4*)(x + (size_t)gr * D_FEAT + k0 + kv);
            As[kv + 0][r] = v.x;
            As[kv + 1][r] = v.y;
            As[kv + 2][r] = v.z;
            As[kv + 3][r] = v.w;
        }
        {
            int k  = tid >> 5;
            int c4 = (tid & 31) * 4;
            *(float4*)(&Bs[k][c4]) = *(const float4*)(W + (size_t)(k0 + k) * HIDDEN + c4);
        }
        __syncthreads();

#pragma unroll
        for (int kk = 0; kk < BK; kk++) {
            float4 a0 = *(float4*)(&As[kk][rowBase]);
            float4 a1 = *(float4*)(&As[kk][rowBase + 4]);
            float4 b0 = *(float4*)(&Bs[kk][colBase]);
            float4 b1 = *(float4*)(&Bs[kk][colBase + 4]);
            float a[8] = {a0.x, a0.y, a0.z, a0.w, a1.x, a1.y, a1.z, a1.w};
            float b[8] = {b0.x, b0.y, b0.z, b0.w, b1.x, b1.y, b1.z, b1.w};
#pragma unroll
            for (int i = 0; i < 8; i++)
#pragma unroll
                for (int j = 0; j < 8; j++)
                    acc[i][j] = fmaf(a[i], b[j], acc[i][j]);
        }
        __syncthreads();
    }

#pragma unroll
    for (int i = 0; i < 8; i++) {
        int gr = blockRow + rowBase + i;
        if (gr < N_NODES) {
            __half2 hpack[4];
            hpack[0] = __floats2half2_rn(acc[i][0], acc[i][1]);
            hpack[1] = __floats2half2_rn(acc[i][2], acc[i][3]);
            hpack[2] = __floats2half2_rn(acc[i][4], acc[i][5]);
            hpack[3] = __floats2half2_rn(acc[i][6], acc[i][7]);
            *(uint4*)(g_h1h + (size_t)gr * HIDDEN + colBase) = *(uint4*)hpack;
        }
    }
}

// ---------------------------------------------------------------------------
// K_agg1: fused layer-1 aggregation + epilogue. One warp per node,
// TWO edges per iteration: half-warp h (lanes h*16..h*16+15) gathers edge
// i+h with LDG.128 (uint4 = 8 halves per lane). Accumulators cover cols
// l16*8..l16*8+8; shfl_xor(16) folds the halves, then 16-lane reduction.
// ---------------------------------------------------------------------------
__global__ __launch_bounds__(256) void k_agg1(const float* __restrict__ b1,
                                              const float* __restrict__ W2,
                                              const float* __restrict__ b2,
                                              float* __restrict__ out) {
    int node = (blockIdx.x * blockDim.x + threadIdx.x) >> 5;
    int lane = threadIdx.x & 31;
    if (node >= N_NODES) return;

    const int half = lane >> 4;          // 0 or 1
    const int l16  = lane & 15;          // 0..15
    const size_t colOff = (size_t)l16 * 8;   // first of 8 halves this lane owns

    int beg = g_row[node];
    int end = beg + g_cnt[node];

    float a[8];
#pragma unroll
    for (int r = 0; r < 8; r++) a[r] = 0.f;

    int i = beg;
    // 4 edges per iteration: 2 pairs, 2 independent uint4 loads per lane
    for (; i + 3 < end; i += 4) {
        int2 e0 = g_csr[i + half];
        int2 e1 = g_csr[i + 2 + half];
        uint4 r0 = *(const uint4*)(g_h1h + (size_t)e0.x * HIDDEN + colOff);
        uint4 r1 = *(const uint4*)(g_h1h + (size_t)e1.x * HIDDEN + colOff);
        float n0 = __int_as_float(e0.y);
        float n1 = __int_as_float(e1.y);
        float2 f;
        f = __half22float2(*(__half2*)&r0.x); a[0] = fmaf(f.x, n0, a[0]); a[1] = fmaf(f.y, n0, a[1]);
        f = __half22float2(*(__half2*)&r0.y); a[2] = fmaf(f.x, n0, a[2]); a[3] = fmaf(f.y, n0, a[3]);
        f = __half22float2(*(__half2*)&r0.z); a[4] = fmaf(f.x, n0, a[4]); a[5] = fmaf(f.y, n0, a[5]);
        f = __half22float2(*(__half2*)&r0.w); a[6] = fmaf(f.x, n0, a[6]); a[7] = fmaf(f.y, n0, a[7]);
        f = __half22float2(*(__half2*)&r1.x); a[0] = fmaf(f.x, n1, a[0]); a[1] = fmaf(f.y, n1, a[1]);
        f = __half22float2(*(__half2*)&r1.y); a[2] = fmaf(f.x, n1, a[2]); a[3] = fmaf(f.y, n1, a[3]);
        f = __half22float2(*(__half2*)&r1.z); a[4] = fmaf(f.x, n1, a[4]); a[5] = fmaf(f.y, n1, a[5]);
        f = __half22float2(*(__half2*)&r1.w); a[6] = fmaf(f.x, n1, a[6]); a[7] = fmaf(f.y, n1, a[7]);
    }
    // pair remainder
    for (; i + 1 < end; i += 2) {
        int2 e0 = g_csr[i + half];
        uint4 r0 = *(const uint4*)(g_h1h + (size_t)e0.x * HIDDEN + colOff);
        float n0 = __int_as_float(e0.y);
        float2 f;
        f = __half22float2(*(__half2*)&r0.x); a[0] = fmaf(f.x, n0, a[0]); a[1] = fmaf(f.y, n0, a[1]);
        f = __half22float2(*(__half2*)&r0.y); a[2] = fmaf(f.x, n0, a[2]); a[3] = fmaf(f.y, n0, a[3]);
        f = __half22float2(*(__half2*)&r0.z); a[4] = fmaf(f.x, n0, a[4]); a[5] = fmaf(f.y, n0, a[5]);
        f = __half22float2(*(__half2*)&r0.w); a[6] = fmaf(f.x, n0, a[6]); a[7] = fmaf(f.y, n0, a[7]);
    }
    // single leftover edge: low half only
    if (i < end && half == 0) {
        int2 e0 = g_csr[i];
        uint4 r0 = *(const uint4*)(g_h1h + (size_t)e0.x * HIDDEN + colOff);
        float n0 = __int_as_float(e0.y);
        float2 f;
        f = __half22float2(*(__half2*)&r0.x); a[0] = fmaf(f.x, n0, a[0]); a[1] = fmaf(f.y, n0, a[1]);
        f = __half22float2(*(__half2*)&r0.y); a[2] = fmaf(f.x, n0, a[2]); a[3] = fmaf(f.y, n0, a[3]);
        f = __half22float2(*(__half2*)&r0.z); a[4] = fmaf(f.x, n0, a[4]); a[5] = fmaf(f.y, n0, a[5]);
        f = __half22float2(*(__half2*)&r0.w); a[6] = fmaf(f.x, n0, a[6]); a[7] = fmaf(f.y, n0, a[7]);
    }

    // fold the two half-warps: after this every lane holds the full col sums
#pragma unroll
    for (int r = 0; r < 8; r++)
        a[r] += __shfl_xor_sync(0xFFFFFFFFu, a[r], 16);

    float di = g_dinv[node];
    float d2 = di * di;

    // self-loop row (fp16), bias, W2 — per-lane 8 cols
    uint4 sr = *(const uint4*)(g_h1h + (size_t)node * HIDDEN + colOff);
    float s[8];
    {
        float2 f;
        f = __half22float2(*(__half2*)&sr.x); s[0] = f.x; s[1] = f.y;
        f = __half22float2(*(__half2*)&sr.y); s[2] = f.x; s[3] = f.y;
        f = __half22float2(*(__half2*)&sr.z); s[4] = f.x; s[5] = f.y;
        f = __half22float2(*(__half2*)&sr.w); s[6] = f.x; s[7] = f.y;
    }
    float4 bb0 = *(const float4*)(b1 + colOff);
    float4 bb1 = *(const float4*)(b1 + colOff + 4);
    float4 w0  = *(const float4*)(W2 + colOff);
    float4 w1  = *(const float4*)(W2 + colOff + 4);
    float bbv[8] = {bb0.x, bb0.y, bb0.z, bb0.w, bb1.x, bb1.y, bb1.z, bb1.w};
    float wv [8] = {w0.x,  w0.y,  w0.z,  w0.w,  w1.x,  w1.y,  w1.z,  w1.w};

    float sum = 0.f;
#pragma unroll
    for (int r = 0; r < 8; r++) {
        float t = fmaxf(fmaf(s[r], d2, a[r]) + bbv[r], 0.0f);
        sum = fmaf(t, wv[r], sum);
    }
    // reduce over the 16 lanes of each half (both halves identical)
#pragma unroll
    for (int off = 8; off > 0; off >>= 1)
        sum += __shfl_xor_sync(0xFFFFFFFFu, sum, off);

    if (lane == 0) {
        g_h2[node] = sum;
        out[node]  = fmaf(sum, d2, b2[0]);  // layer-2 self-loop + bias
    }
}

// ---------------------------------------------------------------------------
// K_agg2: layer-2 gather. One warp per node; lanes stride over in-edges.
// ---------------------------------------------------------------------------
__global__ __launch_bounds__(256) void k_agg2(float* __restrict__ out) {
    int node = (blockIdx.x * blockDim.x + threadIdx.x) >> 5;
    int lane = threadIdx.x & 31;
    if (node >= N_NODES) return;

    int beg = g_row[node];
    int end = beg + g_cnt[node];

    float sum = 0.f;
    for (int i = beg + lane; i < end; i += 32) {
        int2 e = g_csr[i];
        sum = fmaf(g_h2[e.x], __int_as_float(e.y), sum);
    }

#pragma unroll
    for (int off = 16; off > 0; off >>= 1)
        sum += __shfl_xor_sync(0xFFFFFFFFu, sum, off);

    if (lane == 0) out[node] += sum;
}

// ---------------------------------------------------------------------------
// Launch
// ---------------------------------------------------------------------------
extern "C" void kernel_launch(void* const* d_in, const int* in_sizes, int n_in,
                              void* d_out, int out_size) {
    const float* x  = (const float*)d_in[0];
    const void*  ei = d_in[1];
    const float* W1 = (const float*)d_in[2];
    const float* b1 = (const float*)d_in[3];
    const float* W2 = (const float*)d_in[4];
    const float* b2 = (const float*)d_in[5];
    float*       out = (float*)d_out;

    const int T = 256;

    k_prep <<<(N_NODES + T - 1) / T, T>>>(ei);
    k_count<<<(N_EDGES + T - 1) / T, T>>>(ei);
    k_scan1<<<SCAN_B, SCAN_T>>>();
    k_scan3<<<SCAN_B, SCAN_T>>>();
    k_fill <<<(N_EDGES + T - 1) / T, T>>>(ei);
    k_gemm1<<<(N_NODES + BM - 1) / BM, 256>>>(x, W1);
    {
        long long blocks = ((long long)N_NODES * 32 + T - 1) / T;
        k_agg1<<<(unsigned)blocks, T>>>(b1, W2, b2, out);
        k_agg2<<<(unsigned)blocks, T>>>(out);
    }
}

// round 8
// speedup vs baseline: 3.1755x; 1.1193x over previous
#include <cuda_runtime.h>
#include <cuda_fp16.h>
#include <stdint.h>

// Problem constants (fixed by the dataset)
#define N_NODES 50000
#define N_EDGES 800000
#define D_FEAT  128
#define HIDDEN  128

#define SCAN_T   256
#define SCAN_B   ((N_NODES + SCAN_T - 1) / SCAN_T)   // 196

// Scratch (static device globals — no allocation allowed)
__device__ float  g_dinv[N_NODES];
__device__ __half g_h1h[(size_t)N_NODES * HIDDEN];    // x @ W1 (fp16)
__device__ float  g_h2 [N_NODES];                     // relu(.) @ W2 per node
__device__ int    g_cnt   [N_NODES];                  // in-degree (no self loop)
__device__ int    g_cursor[N_NODES];
__device__ int    g_row   [N_NODES];                  // CSR row starts
__device__ int    g_bsum  [SCAN_B];
__device__ int2   g_csr   [N_EDGES];                  // packed {src, norm-bits}
__device__ int    g_is64;

// ---------------------------------------------------------------------------
// Edge fetch helper (dtype decided by runtime probe)
// ---------------------------------------------------------------------------
__device__ __forceinline__ void load_edge(const void* ei, int i, int& s, int& d) {
    if (g_is64) {
        const long long* p = (const long long*)ei;
        s = (int)p[i];
        d = (int)p[i + N_EDGES];
    } else {
        const int* p = (const int*)ei;
        s = p[i];
        d = p[i + N_EDGES];
    }
    s = min(max(s, 0), N_NODES - 1);
    d = min(max(d, 0), N_NODES - 1);
}

// ---------------------------------------------------------------------------
// K_prep: zero counters; global thread 0 probes edge dtype.
// ---------------------------------------------------------------------------
__global__ void k_prep(const void* __restrict__ ei) {
    int i = blockIdx.x * blockDim.x + threadIdx.x;
    if (i < N_NODES) { g_cnt[i] = 0; g_cursor[i] = 0; }
    if (i == 0) {
        const long long* p = (const long long*)ei;
        int ok64 = 1;
        for (int k = 0; k < 16; k++) {
            long long v = p[k];
            if (v < 0 || v >= N_NODES) { ok64 = 0; break; }
        }
        g_is64 = ok64;
    }
}

// ---------------------------------------------------------------------------
// K_count: in-degree counts straight from edge_index
// ---------------------------------------------------------------------------
__global__ void k_count(const void* __restrict__ ei) {
    int i = blockIdx.x * blockDim.x + threadIdx.x;
    if (i < N_EDGES) {
        int s, d;
        load_edge(ei, i, s, d);
        atomicAdd(&g_cnt[d], 1);
    }
}

// ---------------------------------------------------------------------------
// Scan step 1: per-block sums of g_cnt; also dinv = rsqrt(1+cnt) (fused)
// ---------------------------------------------------------------------------
__global__ void k_scan1() {
    __shared__ int sh[SCAN_T];
    int i = blockIdx.x * SCAN_T + threadIdx.x;
    int c = (i < N_NODES) ? g_cnt[i] : 0;
    if (i < N_NODES) g_dinv[i] = rsqrtf((float)(1 + c));
    sh[threadIdx.x] = c;
    __syncthreads();
    for (int s = SCAN_T / 2; s > 0; s >>= 1) {
        if (threadIdx.x < s) sh[threadIdx.x] += sh[threadIdx.x + s];
        __syncthreads();
    }
    if (threadIdx.x == 0) g_bsum[blockIdx.x] = sh[0];
}

// ---------------------------------------------------------------------------
// Scan step 2 (fused): every block redundantly scans the 196 block sums,
// then its local 256-element exclusive scan -> g_row.
// ---------------------------------------------------------------------------
__global__ void k_scan3() {
    __shared__ int shb[SCAN_T];
    __shared__ int sh [SCAN_T];

    int bv = (threadIdx.x < SCAN_B) ? g_bsum[threadIdx.x] : 0;
    shb[threadIdx.x] = bv;
    __syncthreads();
    for (int off = 1; off < SCAN_T; off <<= 1) {
        int t = (threadIdx.x >= off) ? shb[threadIdx.x - off] : 0;
        __syncthreads();
        shb[threadIdx.x] += t;
        __syncthreads();
    }
    int blockOff = shb[blockIdx.x] - g_bsum[blockIdx.x];

    int i = blockIdx.x * SCAN_T + threadIdx.x;
    int v = (i < N_NODES) ? g_cnt[i] : 0;
    sh[threadIdx.x] = v;
    __syncthreads();
    for (int off = 1; off < SCAN_T; off <<= 1) {
        int t = (threadIdx.x >= off) ? sh[threadIdx.x - off] : 0;
        __syncthreads();
        sh[threadIdx.x] += t;
        __syncthreads();
    }
    if (i < N_NODES)
        g_row[i] = blockOff + sh[threadIdx.x] - v;
}

// ---------------------------------------------------------------------------
// K_fill: place edges into CSR slots; packed {src, norm}
// ---------------------------------------------------------------------------
__global__ void k_fill(const void* __restrict__ ei) {
    int e = blockIdx.x * blockDim.x + threadIdx.x;
    if (e < N_EDGES) {
        int src, dst;
        load_edge(ei, e, src, dst);
        int pos = atomicAdd(&g_cursor[dst], 1);
        float norm = g_dinv[src] * g_dinv[dst];
        g_csr[g_row[dst] + pos] = make_int2(src, __float_as_int(norm));
    }
}

// ---------------------------------------------------------------------------
// K3: h1 = x @ W1.  BM=128, BN=128, BK=8, 256 threads, 8x8 per-thread tile.
// Epilogue writes fp16 only. Runs on a forked stream, overlapped with CSR build.
// ---------------------------------------------------------------------------
#define BM 128
#define BN 128
#define BK 8

__global__ __launch_bounds__(256) void k_gemm1(const float* __restrict__ x,
                                               const float* __restrict__ W) {
    __shared__ float As[BK][BM];
    __shared__ float Bs[BK][BN];

    const int tid = threadIdx.x;
    const int blockRow = blockIdx.x * BM;
    const int rowBase = (tid >> 4) * 8;
    const int colBase = (tid & 15) * 8;

    float acc[8][8];
#pragma unroll
    for (int i = 0; i < 8; i++)
#pragma unroll
        for (int j = 0; j < 8; j++) acc[i][j] = 0.0f;

    for (int k0 = 0; k0 < D_FEAT; k0 += BK) {
        {
            int r  = tid >> 1;
            int kv = (tid & 1) * 4;
            int gr = blockRow + r;
            float4 v = make_float4(0.f, 0.f, 0.f, 0.f);
            if (gr < N_NODES)
                v = *(const float4*)(x + (size_t)gr * D_FEAT + k0 + kv);
            As[kv + 0][r] = v.x;
            As[kv + 1][r] = v.y;
            As[kv + 2][r] = v.z;
            As[kv + 3][r] = v.w;
        }
        {
            int k  = tid >> 5;
            int c4 = (tid & 31) * 4;
            *(float4*)(&Bs[k][c4]) = *(const float4*)(W + (size_t)(k0 + k) * HIDDEN + c4);
        }
        __syncthreads();

#pragma unroll
        for (int kk = 0; kk < BK; kk++) {
            float4 a0 = *(float4*)(&As[kk][rowBase]);
            float4 a1 = *(float4*)(&As[kk][rowBase + 4]);
            float4 b0 = *(float4*)(&Bs[kk][colBase]);
            float4 b1 = *(float4*)(&Bs[kk][colBase + 4]);
            float a[8] = {a0.x, a0.y, a0.z, a0.w, a1.x, a1.y, a1.z, a1.w};
            float b[8] = {b0.x, b0.y, b0.z, b0.w, b1.x, b1.y, b1.z, b1.w};
#pragma unroll
            for (int i = 0; i < 8; i++)
#pragma unroll
                for (int j = 0; j < 8; j++)
                    acc[i][j] = fmaf(a[i], b[j], acc[i][j]);
        }
        __syncthreads();
    }

#pragma unroll
    for (int i = 0; i < 8; i++) {
        int gr = blockRow + rowBase + i;
        if (gr < N_NODES) {
            __half2 hpack[4];
            hpack[0] = __floats2half2_rn(acc[i][0], acc[i][1]);
            hpack[1] = __floats2half2_rn(acc[i][2], acc[i][3]);
            hpack[2] = __floats2half2_rn(acc[i][4], acc[i][5]);
            hpack[3] = __floats2half2_rn(acc[i][6], acc[i][7]);
            *(uint4*)(g_h1h + (size_t)gr * HIDDEN + colBase) = *(uint4*)hpack;
        }
    }
}

// ---------------------------------------------------------------------------
// Macro: accumulate one fp16 row (uint4 = 8 halves) scaled by n into a[8]
// ---------------------------------------------------------------------------
#define ACC_ROW(r_, n_)                                                        \
    do {                                                                       \
        float2 f_;                                                             \
        f_ = __half22float2(*(__half2*)&(r_).x);                               \
        a[0] = fmaf(f_.x, (n_), a[0]); a[1] = fmaf(f_.y, (n_), a[1]);          \
        f_ = __half22float2(*(__half2*)&(r_).y);                               \
        a[2] = fmaf(f_.x, (n_), a[2]); a[3] = fmaf(f_.y, (n_), a[3]);          \
        f_ = __half22float2(*(__half2*)&(r_).z);                               \
        a[4] = fmaf(f_.x, (n_), a[4]); a[5] = fmaf(f_.y, (n_), a[5]);          \
        f_ = __half22float2(*(__half2*)&(r_).w);                               \
        a[6] = fmaf(f_.x, (n_), a[6]); a[7] = fmaf(f_.y, (n_), a[7]);          \
    } while (0)

// ---------------------------------------------------------------------------
// K_agg1: fused layer-1 aggregation + epilogue. One warp per node,
// 2 edges per "slot": half-warp h gathers edge i+h via LDG.128; 8-edge
// unroll gives each lane 4 independent loads in flight.
// ---------------------------------------------------------------------------
__global__ __launch_bounds__(256) void k_agg1(const float* __restrict__ b1,
                                              const float* __restrict__ W2,
                                              const float* __restrict__ b2,
                                              float* __restrict__ out) {
    int node = (blockIdx.x * blockDim.x + threadIdx.x) >> 5;
    int lane = threadIdx.x & 31;
    if (node >= N_NODES) return;

    const int half = lane >> 4;              // 0 or 1
    const int l16  = lane & 15;              // 0..15
    const size_t colOff = (size_t)l16 * 8;   // 8 halves per lane

    int beg = g_row[node];
    int end = beg + g_cnt[node];

    float a[8];
#pragma unroll
    for (int r = 0; r < 8; r++) a[r] = 0.f;

    int i = beg;
    // 8 edges per iteration: 4 independent uint4 loads per lane
    for (; i + 7 < end; i += 8) {
        int2 e0 = g_csr[i +     half];
        int2 e1 = g_csr[i + 2 + half];
        int2 e2 = g_csr[i + 4 + half];
        int2 e3 = g_csr[i + 6 + half];
        uint4 r0 = *(const uint4*)(g_h1h + (size_t)e0.x * HIDDEN + colOff);
        uint4 r1 = *(const uint4*)(g_h1h + (size_t)e1.x * HIDDEN + colOff);
        uint4 r2 = *(const uint4*)(g_h1h + (size_t)e2.x * HIDDEN + colOff);
        uint4 r3 = *(const uint4*)(g_h1h + (size_t)e3.x * HIDDEN + colOff);
        float n0 = __int_as_float(e0.y);
        float n1 = __int_as_float(e1.y);
        float n2 = __int_as_float(e2.y);
        float n3 = __int_as_float(e3.y);
        ACC_ROW(r0, n0); ACC_ROW(r1, n1); ACC_ROW(r2, n2); ACC_ROW(r3, n3);
    }
    for (; i + 3 < end; i += 4) {
        int2 e0 = g_csr[i +     half];
        int2 e1 = g_csr[i + 2 + half];
        uint4 r0 = *(const uint4*)(g_h1h + (size_t)e0.x * HIDDEN + colOff);
        uint4 r1 = *(const uint4*)(g_h1h + (size_t)e1.x * HIDDEN + colOff);
        float n0 = __int_as_float(e0.y);
        float n1 = __int_as_float(e1.y);
        ACC_ROW(r0, n0); ACC_ROW(r1, n1);
    }
    for (; i + 1 < end; i += 2) {
        int2 e0 = g_csr[i + half];
        uint4 r0 = *(const uint4*)(g_h1h + (size_t)e0.x * HIDDEN + colOff);
        float n0 = __int_as_float(e0.y);
        ACC_ROW(r0, n0);
    }
    if (i < end && half == 0) {
        int2 e0 = g_csr[i];
        uint4 r0 = *(const uint4*)(g_h1h + (size_t)e0.x * HIDDEN + colOff);
        float n0 = __int_as_float(e0.y);
        ACC_ROW(r0, n0);
    }

    // fold the two half-warps
#pragma unroll
    for (int r = 0; r < 8; r++)
        a[r] += __shfl_xor_sync(0xFFFFFFFFu, a[r], 16);

    float di = g_dinv[node];
    float d2 = di * di;

    uint4 sr = *(const uint4*)(g_h1h + (size_t)node * HIDDEN + colOff);
    float s[8];
    {
        float2 f;
        f = __half22float2(*(__half2*)&sr.x); s[0] = f.x; s[1] = f.y;
        f = __half22float2(*(__half2*)&sr.y); s[2] = f.x; s[3] = f.y;
        f = __half22float2(*(__half2*)&sr.z); s[4] = f.x; s[5] = f.y;
        f = __half22float2(*(__half2*)&sr.w); s[6] = f.x; s[7] = f.y;
    }
    float4 bb0 = *(const float4*)(b1 + colOff);
    float4 bb1 = *(const float4*)(b1 + colOff + 4);
    float4 w0  = *(const float4*)(W2 + colOff);
    float4 w1  = *(const float4*)(W2 + colOff + 4);
    float bbv[8] = {bb0.x, bb0.y, bb0.z, bb0.w, bb1.x, bb1.y, bb1.z, bb1.w};
    float wv [8] = {w0.x,  w0.y,  w0.z,  w0.w,  w1.x,  w1.y,  w1.z,  w1.w};

    float sum = 0.f;
#pragma unroll
    for (int r = 0; r < 8; r++) {
        float t = fmaxf(fmaf(s[r], d2, a[r]) + bbv[r], 0.0f);
        sum = fmaf(t, wv[r], sum);
    }
#pragma unroll
    for (int off = 8; off > 0; off >>= 1)
        sum += __shfl_xor_sync(0xFFFFFFFFu, sum, off);

    if (lane == 0) {
        g_h2[node] = sum;
        out[node]  = fmaf(sum, d2, b2[0]);  // layer-2 self-loop + bias
    }
}

// ---------------------------------------------------------------------------
// K_agg2: layer-2 gather. One warp per node; lanes stride over in-edges.
// ---------------------------------------------------------------------------
__global__ __launch_bounds__(256) void k_agg2(float* __restrict__ out) {
    int node = (blockIdx.x * blockDim.x + threadIdx.x) >> 5;
    int lane = threadIdx.x & 31;
    if (node >= N_NODES) return;

    int beg = g_row[node];
    int end = beg + g_cnt[node];

    float sum = 0.f;
    for (int i = beg + lane; i < end; i += 32) {
        int2 e = g_csr[i];
        sum = fmaf(g_h2[e.x], __int_as_float(e.y), sum);
    }

#pragma unroll
    for (int off = 16; off > 0; off >>= 1)
        sum += __shfl_xor_sync(0xFFFFFFFFu, sum, off);

    if (lane == 0) out[node] += sum;
}

// ---------------------------------------------------------------------------
// Launch. GEMM is independent of the CSR build, so it runs on a forked
// side stream (fork/join via events — capture-legal, no syncs, no allocs
// of device memory; stream/events created once on the first, uncaptured,
// correctness call and reused so the captured graph is deterministic).
// ---------------------------------------------------------------------------
extern "C" void kernel_launch(void* const* d_in, const int* in_sizes, int n_in,
                              void* d_out, int out_size) {
    const float* x  = (const float*)d_in[0];
    const void*  ei = d_in[1];
    const float* W1 = (const float*)d_in[2];
    const float* b1 = (const float*)d_in[3];
    const float* W2 = (const float*)d_in[4];
    const float* b2 = (const float*)d_in[5];
    float*       out = (float*)d_out;

    static cudaStream_t s2 = nullptr;
    static cudaEvent_t  evFork = nullptr, evJoin = nullptr;
    if (s2 == nullptr) {
        cudaStreamCreateWithFlags(&s2, cudaStreamNonBlocking);
        cudaEventCreateWithFlags(&evFork, cudaEventDisableTiming);
        cudaEventCreateWithFlags(&evJoin, cudaEventDisableTiming);
    }

    const int T = 256;

    // Fork: GEMM on side stream (depends only on x, W1)
    cudaEventRecord(evFork, 0);
    cudaStreamWaitEvent(s2, evFork, 0);
    k_gemm1<<<(N_NODES + BM - 1) / BM, 256, 0, s2>>>(x, W1);
    cudaEventRecord(evJoin, s2);

    // CSR build chain on main stream
    k_prep <<<(N_NODES + T - 1) / T, T>>>(ei);
    k_count<<<(N_EDGES + T - 1) / T, T>>>(ei);
    k_scan1<<<SCAN_B, SCAN_T>>>();
    k_scan3<<<SCAN_B, SCAN_T>>>();
    k_fill <<<(N_EDGES + T - 1) / T, T>>>(ei);

    // Join: aggregation needs both CSR and h1
    cudaStreamWaitEvent(0, evJoin, 0);
    {
        long long blocks = ((long long)N_NODES * 32 + T - 1) / T;
        k_agg1<<<(unsigned)blocks, T>>>(b1, W2, b2, out);
        k_agg2<<<(unsigned)blocks, T>>>(out);
    }
}